// round 5
// baseline (speedup 1.0000x reference)
#include <cuda_runtime.h>
#include <cuda_bf16.h>
#include <cstdint>

#define NHEADS 20
#define HEAD_DIM 64
#define HIDDEN 1280
#define CROSS 2048
#define NB 4
#define SQ 4096
#define TXT 77
#define NTOK 4
#define ENC (TXT + NTOK)

// ============================================================================
// PTX helpers (baseline-family only: mma.sync / ldmatrix / cp.async)
// ============================================================================
__device__ __forceinline__ uint32_t smem_to_u32(const void* smem_ptr) {
    uint32_t addr;
    asm("{ .reg .u64 tmp; cvta.to.shared.u64 tmp, %1; cvt.u32.u64 %0, tmp; }"
        : "=r"(addr) : "l"(smem_ptr));
    return addr;
}

__device__ __forceinline__ void cp_async16(uint32_t dst, const void* src, int bytes) {
    asm volatile("cp.async.cg.shared.global [%0], [%1], 16, %2;"
                 :: "r"(dst), "l"(src), "r"(bytes));
}
#define CP_COMMIT() asm volatile("cp.async.commit_group;" ::: "memory")
#define CP_WAIT(N)  asm volatile("cp.async.wait_group %0;" :: "n"(N) : "memory")

__device__ __forceinline__ void ldsm_x4(uint32_t* r, uint32_t a) {
    asm volatile("ldmatrix.sync.aligned.m8n8.x4.shared.b16 {%0,%1,%2,%3}, [%4];"
                 : "=r"(r[0]), "=r"(r[1]), "=r"(r[2]), "=r"(r[3]) : "r"(a));
}

__device__ __forceinline__ void mma16816(float* c, const uint32_t* a,
                                         uint32_t b0, uint32_t b1) {
    asm volatile(
        "mma.sync.aligned.m16n8k16.row.col.f32.bf16.bf16.f32 "
        "{%0,%1,%2,%3},{%4,%5,%6,%7},{%8,%9},{%0,%1,%2,%3};"
        : "+f"(c[0]), "+f"(c[1]), "+f"(c[2]), "+f"(c[3])
        : "r"(a[0]), "r"(a[1]), "r"(a[2]), "r"(a[3]), "r"(b0), "r"(b1));
}

// ============================================================================
// Scratch (static device allocations)
// ============================================================================
__device__ __nv_bfloat16 g_ahi[NB * SQ * HIDDEN];
__device__ __nv_bfloat16 g_alo[NB * SQ * HIDDEN];
__device__ __nv_bfloat16 g_ehi[NB * ENC * CROSS];
__device__ __nv_bfloat16 g_elo[NB * ENC * CROSS];
__device__ __nv_bfloat16 g_wqT_hi[HIDDEN * HIDDEN];
__device__ __nv_bfloat16 g_wqT_lo[HIDDEN * HIDDEN];
__device__ __nv_bfloat16 g_wT_hi[4 * HIDDEN * CROSS];
__device__ __nv_bfloat16 g_wT_lo[4 * HIDDEN * CROSS];
__device__ __nv_bfloat16 g_woutT_hi[HIDDEN * HIDDEN];
__device__ __nv_bfloat16 g_woutT_lo[HIDDEN * HIDDEN];
__device__ float g_q[NB * SQ * HIDDEN];
__device__ float g_kv[4 * NB * TXT * HIDDEN];

// ============================================================================
// fp32 -> bf16 hi/lo split
// ============================================================================
__global__ __launch_bounds__(256)
void split_kernel(const float* __restrict__ in, __nv_bfloat16* __restrict__ hi,
                  __nv_bfloat16* __restrict__ lo, int n4)
{
    int i = blockIdx.x * blockDim.x + threadIdx.x;
    if (i >= n4) return;
    float4 x = ((const float4*)in)[i];
    __nv_bfloat16 h0 = __float2bfloat16(x.x);
    __nv_bfloat16 h1 = __float2bfloat16(x.y);
    __nv_bfloat16 h2 = __float2bfloat16(x.z);
    __nv_bfloat16 h3 = __float2bfloat16(x.w);
    __nv_bfloat162 hA; hA.x = h0; hA.y = h1;
    __nv_bfloat162 hB; hB.x = h2; hB.y = h3;
    ((__nv_bfloat162*)hi)[2 * i]     = hA;
    ((__nv_bfloat162*)hi)[2 * i + 1] = hB;
    __nv_bfloat162 lA;
    lA.x = __float2bfloat16(x.x - __bfloat162float(h0));
    lA.y = __float2bfloat16(x.y - __bfloat162float(h1));
    __nv_bfloat162 lB;
    lB.x = __float2bfloat16(x.z - __bfloat162float(h2));
    lB.y = __float2bfloat16(x.w - __bfloat162float(h3));
    ((__nv_bfloat162*)lo)[2 * i]     = lA;
    ((__nv_bfloat162*)lo)[2 * i + 1] = lB;
}

// ============================================================================
// Merged transpose + split of all 6 weights (grid.z selects weight).
// ============================================================================
struct TSArgs {
    const float* src[6];
    __nv_bfloat16* dhi[6];
    __nv_bfloat16* dlo[6];
    int K[6];
};

__global__ __launch_bounds__(256)
void transpose_split_all(TSArgs args)
{
    const int w = blockIdx.z;
    const int K = args.K[w];
    const int k0 = blockIdx.y * 32;
    if (k0 >= K) return;
    const float* in = args.src[w];
    __nv_bfloat16* ohi = args.dhi[w];
    __nv_bfloat16* olo = args.dlo[w];

    __shared__ float t[32][33];
    const int tx = threadIdx.x, ty = threadIdx.y;
    const int n0 = blockIdx.x * 32;
    #pragma unroll
    for (int j = ty; j < 32; j += 8)
        t[j][tx] = in[(long)(k0 + j) * HIDDEN + n0 + tx];
    __syncthreads();
    #pragma unroll
    for (int j = ty; j < 32; j += 8) {
        float x = t[tx][j];
        __nv_bfloat16 h = __float2bfloat16(x);
        long o = (long)(n0 + j) * K + k0 + tx;
        ohi[o] = h;
        olo[o] = __float2bfloat16(x - __bfloat162float(h));
    }
}

// ============================================================================
// HMMA GEMM: C[M,N] = (Ahi+Alo)[M,K] @ (Bhi+Blo)^T  (B stored [N][K] bf16)
// CTA tile 128x256x32, 8 warps, warp tile 64x64 (wm=2, wn=4).
// cp.async double buffer, 3-term bf16 split, fused bias+residual option.
// ============================================================================
#define LDS_ROW 80
#define A_STG   10240      // 128 rows * 80B
#define B_STG   20480      // 256 rows * 80B
#define OFF_AHI 0          // + b*A_STG   [0, 20480)
#define OFF_ALO 20480      // + b*A_STG   [20480, 40960)
#define OFF_BHI 40960      // + b*B_STG   [40960, 81920)
#define OFF_BLO 81920      // + b*B_STG   [81920, 122880)
#define SMEM_TOT 122880

struct GemmArgs {
    const __nv_bfloat16 *Ahi, *Alo, *Bhi, *Blo;
    float* C;
    long aBatch, cBatch;
    int Mvalid, K, ldc;
    const float *bias, *resid;
    int kvmode;
};

__device__ __forceinline__ void gemm_load_stage(
    uint32_t smb, int s, int tid, int rowBase, int colBase, int Mvalid, int K,
    const __nv_bfloat16* __restrict__ Ahi, const __nv_bfloat16* __restrict__ Alo,
    const __nv_bfloat16* __restrict__ Bhi, const __nv_bfloat16* __restrict__ Blo)
{
    const int b = s & 1;
    const long k0 = (long)s << 5;
    // A: 128 rows x 4 chunks of 16B (hi + lo)
    #pragma unroll
    for (int i = 0; i < 2; i++) {
        int idx = tid + i * 256;          // 0..511
        int r = idx >> 2, c = idx & 3;
        uint32_t d = smb + (uint32_t)(b * A_STG + r * LDS_ROW + c * 16);
        long go = ((long)(rowBase + r)) * K + k0 + c * 8;
        int bytes = (rowBase + r < Mvalid) ? 16 : 0;
        cp_async16(d + OFF_AHI, Ahi + go, bytes);
        cp_async16(d + OFF_ALO, Alo + go, bytes);
    }
    // B: 256 rows x 4 chunks of 16B (hi + lo)
    #pragma unroll
    for (int i = 0; i < 4; i++) {
        int idx = tid + i * 256;          // 0..1023
        int r = idx >> 2, c = idx & 3;
        uint32_t d = smb + (uint32_t)(b * B_STG + r * LDS_ROW + c * 16);
        long gb = ((long)(colBase + r)) * K + k0 + c * 8;
        cp_async16(d + OFF_BHI, Bhi + gb, 16);
        cp_async16(d + OFF_BLO, Blo + gb, 16);
    }
    CP_COMMIT();
}

__global__ __launch_bounds__(256)
void hmma_gemm(GemmArgs args)
{
    extern __shared__ __align__(16) char smx[];
    const uint32_t smb = smem_to_u32(smx);
    const int tid = threadIdx.x;

    const __nv_bfloat16* Ahi = args.Ahi;
    const __nv_bfloat16* Alo = args.Alo;
    const __nv_bfloat16* Bhi = args.Bhi;
    const __nv_bfloat16* Blo = args.Blo;
    float* C = args.C;
    int Mvalid = args.Mvalid;
    const int K = args.K, ldc = args.ldc;

    if (args.kvmode) {
        const int gemm = blockIdx.z >> 2;
        const int batch = blockIdx.z & 3;
        const long aoff = (long)batch * ENC * CROSS + (gemm >= 2 ? (long)TXT * CROSS : 0);
        Ahi += aoff;  Alo += aoff;
        Bhi += (long)gemm * HIDDEN * CROSS;
        Blo += (long)gemm * HIDDEN * CROSS;
        C   += ((long)gemm * NB + batch) * TXT * HIDDEN;
        Mvalid = (gemm < 2) ? TXT : NTOK;
    } else {
        Ahi += blockIdx.z * args.aBatch;
        Alo += blockIdx.z * args.aBatch;
        C   += blockIdx.z * args.cBatch;
    }

    const int rowBase = blockIdx.y * 128;
    const int colBase = blockIdx.x * 256;
    const int NS = K >> 5;

    const int warp = tid >> 5, lane = tid & 31;
    const int wm = warp >> 2, wn = warp & 3;   // wm: 2, wn: 4
    const int m0 = wm * 64, n0 = wn * 64;

    const uint32_t aoffs = (uint32_t)((m0 + (lane & 15)) * LDS_ROW + (lane >> 4) * 16);
    const uint32_t boffs = (uint32_t)((n0 + ((lane >> 4) & 1) * 8 + (lane & 7)) * LDS_ROW
                                      + ((lane >> 3) & 1) * 16);

    float acc[4][8][4];
    #pragma unroll
    for (int mi = 0; mi < 4; mi++)
        #pragma unroll
        for (int nj = 0; nj < 8; nj++)
            #pragma unroll
            for (int t = 0; t < 4; t++) acc[mi][nj][t] = 0.f;

    gemm_load_stage(smb, 0, tid, rowBase, colBase, Mvalid, K, Ahi, Alo, Bhi, Blo);

    for (int s = 0; s < NS; ++s) {
        if (s + 1 < NS) {
            gemm_load_stage(smb, s + 1, tid, rowBase, colBase, Mvalid, K, Ahi, Alo, Bhi, Blo);
            CP_WAIT(1);
        } else {
            CP_WAIT(0);
        }
        __syncthreads();

        const int b = s & 1;
        const uint32_t aHi = smb + OFF_AHI + b * A_STG;
        const uint32_t aLo = smb + OFF_ALO + b * A_STG;
        const uint32_t bHi = smb + OFF_BHI + b * B_STG;
        const uint32_t bLo = smb + OFF_BLO + b * B_STG;

        #pragma unroll
        for (int ks = 0; ks < 2; ks++) {
            uint32_t Ah[4][4], Al[4][4];
            #pragma unroll
            for (int mi = 0; mi < 4; mi++) {
                ldsm_x4(Ah[mi], aHi + aoffs + mi * 16 * LDS_ROW + ks * 32);
                ldsm_x4(Al[mi], aLo + aoffs + mi * 16 * LDS_ROW + ks * 32);
            }
            #pragma unroll
            for (int half = 0; half < 2; half++) {
                uint32_t Bh[2][4], Bl[2][4];
                #pragma unroll
                for (int nn = 0; nn < 2; nn++) {
                    const uint32_t bo = boffs + (half * 2 + nn) * 16 * LDS_ROW + ks * 32;
                    ldsm_x4(Bh[nn], bHi + bo);
                    ldsm_x4(Bl[nn], bLo + bo);
                }
                // burst 1: hi*hi (8 independent tiles x 4 mi)
                #pragma unroll
                for (int mi = 0; mi < 4; mi++)
                    #pragma unroll
                    for (int j4 = 0; j4 < 4; j4++) {
                        const int ni = j4 >> 1, h = (j4 & 1) * 2;
                        mma16816(acc[mi][half * 4 + j4], Ah[mi], Bh[ni][h], Bh[ni][h + 1]);
                    }
                // burst 2: hi*lo
                #pragma unroll
                for (int mi = 0; mi < 4; mi++)
                    #pragma unroll
                    for (int j4 = 0; j4 < 4; j4++) {
                        const int ni = j4 >> 1, h = (j4 & 1) * 2;
                        mma16816(acc[mi][half * 4 + j4], Ah[mi], Bl[ni][h], Bl[ni][h + 1]);
                    }
                // burst 3: lo*hi
                #pragma unroll
                for (int mi = 0; mi < 4; mi++)
                    #pragma unroll
                    for (int j4 = 0; j4 < 4; j4++) {
                        const int ni = j4 >> 1, h = (j4 & 1) * 2;
                        mma16816(acc[mi][half * 4 + j4], Al[mi], Bh[ni][h], Bh[ni][h + 1]);
                    }
            }
        }
        __syncthreads();
    }

    // Epilogue
    const int g = lane >> 2, tig = lane & 3;
    const float* bias = args.bias;
    const float* resid = args.resid;
    #pragma unroll
    for (int mi = 0; mi < 4; mi++) {
        #pragma unroll
        for (int nj = 0; nj < 8; nj++) {
            const int r0 = rowBase + m0 + mi * 16 + g;
            const int col = colBase + n0 + nj * 8 + tig * 2;
            float2 v0 = make_float2(acc[mi][nj][0], acc[mi][nj][1]);
            float2 v1 = make_float2(acc[mi][nj][2], acc[mi][nj][3]);
            if (bias) {
                const float2 bi = *(const float2*)(bias + col);
                v0.x += bi.x; v0.y += bi.y;
                v1.x += bi.x; v1.y += bi.y;
                if (r0 < Mvalid) {
                    const float2 rr = *(const float2*)(resid + (long)r0 * ldc + col);
                    v0.x += rr.x; v0.y += rr.y;
                }
                if (r0 + 8 < Mvalid) {
                    const float2 rr = *(const float2*)(resid + (long)(r0 + 8) * ldc + col);
                    v1.x += rr.x; v1.y += rr.y;
                }
            }
            if (r0 < Mvalid)     *(float2*)(C + (long)r0 * ldc + col)       = v0;
            if (r0 + 8 < Mvalid) *(float2*)(C + (long)(r0 + 8) * ldc + col) = v1;
        }
    }
}

// ============================================================================
// Attention: online softmax single-pass, per-thread q-row, K/V in smem.
// Writes bf16 hi/lo split output directly.
// ============================================================================
__global__ __launch_bounds__(128)
void attn_kernel(const float* __restrict__ q, const float* __restrict__ kv,
                 __nv_bfloat16* __restrict__ ohi, __nv_bfloat16* __restrict__ olo)
{
    __shared__ float ks[TXT][HEAD_DIM];
    __shared__ float vs[TXT][HEAD_DIM];
    __shared__ float ipks[NTOK][HEAD_DIM];
    __shared__ float ipvs[NTOK][HEAD_DIM];

    const int b   = blockIdx.z;
    const int h   = blockIdx.y;
    const int row = blockIdx.x * blockDim.x + threadIdx.x;

    const long slab = (long)NB * TXT * HIDDEN;
    const float* k   = kv;
    const float* v   = kv + slab;
    const float* ipk = kv + 2 * slab;
    const float* ipv = kv + 3 * slab;

    for (int i = threadIdx.x; i < TXT * (HEAD_DIM / 4); i += blockDim.x) {
        int r = i >> 4, c4 = (i & 15) * 4;
        long off = ((long)b * TXT + r) * HIDDEN + h * HEAD_DIM + c4;
        *(float4*)&ks[r][c4] = *(const float4*)(k + off);
        *(float4*)&vs[r][c4] = *(const float4*)(v + off);
    }
    for (int i = threadIdx.x; i < NTOK * (HEAD_DIM / 4); i += blockDim.x) {
        int r = i >> 4, c4 = (i & 15) * 4;
        long off = ((long)b * TXT + r) * HIDDEN + h * HEAD_DIM + c4;
        *(float4*)&ipks[r][c4] = *(const float4*)(ipk + off);
        *(float4*)&ipvs[r][c4] = *(const float4*)(ipv + off);
    }
    __syncthreads();

    float qr[HEAD_DIM];
    {
        const float* qp = q + ((long)b * SQ + row) * HIDDEN + h * HEAD_DIM;
        #pragma unroll
        for (int i = 0; i < 16; i++) {
            float4 t = *(const float4*)(qp + i * 4);
            qr[4 * i + 0] = t.x; qr[4 * i + 1] = t.y;
            qr[4 * i + 2] = t.z; qr[4 * i + 3] = t.w;
        }
    }

    const float scale = 0.125f;

    float acc[HEAD_DIM];
    #pragma unroll
    for (int d = 0; d < HEAD_DIM; d++) acc[d] = 0.f;
    float m = -1e30f, l = 0.f;

    for (int key = 0; key < TXT; key++) {
        const float4* kk4 = (const float4*)ks[key];
        float s = 0.f;
        #pragma unroll
        for (int i = 0; i < 16; i++) {
            float4 t = kk4[i];
            s = fmaf(qr[4*i+0], t.x, s);
            s = fmaf(qr[4*i+1], t.y, s);
            s = fmaf(qr[4*i+2], t.z, s);
            s = fmaf(qr[4*i+3], t.w, s);
        }
        s *= scale;
        if (s > m) {
            float corr = __expf(m - s);
            l *= corr;
            #pragma unroll
            for (int d = 0; d < HEAD_DIM; d++) acc[d] *= corr;
            m = s;
        }
        float p = __expf(s - m);
        l += p;
        const float4* vv4 = (const float4*)vs[key];
        #pragma unroll
        for (int i = 0; i < 16; i++) {
            float4 t = vv4[i];
            acc[4*i+0] = fmaf(p, t.x, acc[4*i+0]);
            acc[4*i+1] = fmaf(p, t.y, acc[4*i+1]);
            acc[4*i+2] = fmaf(p, t.z, acc[4*i+2]);
            acc[4*i+3] = fmaf(p, t.w, acc[4*i+3]);
        }
    }
    float inv = 1.f / l;
    #pragma unroll
    for (int d = 0; d < HEAD_DIM; d++) acc[d] *= inv;

    if (b & 1) {
        float smv[NTOK];
        float m2 = -1e30f;
        #pragma unroll
        for (int key = 0; key < NTOK; key++) {
            const float4* kk4 = (const float4*)ipks[key];
            float s = 0.f;
            #pragma unroll
            for (int i = 0; i < 16; i++) {
                float4 t = kk4[i];
                s = fmaf(qr[4*i+0], t.x, s);
                s = fmaf(qr[4*i+1], t.y, s);
                s = fmaf(qr[4*i+2], t.z, s);
                s = fmaf(qr[4*i+3], t.w, s);
            }
            smv[key] = s * scale;
            m2 = fmaxf(m2, smv[key]);
        }
        float l2 = 0.f;
        float p[NTOK];
        #pragma unroll
        for (int key = 0; key < NTOK; key++) { p[key] = __expf(smv[key] - m2); l2 += p[key]; }
        float inv2 = 1.f / l2;
        #pragma unroll
        for (int key = 0; key < NTOK; key++) {
            float pw = p[key] * inv2;
            const float4* vv4 = (const float4*)ipvs[key];
            #pragma unroll
            for (int i = 0; i < 16; i++) {
                float4 t = vv4[i];
                acc[4*i+0] = fmaf(pw, t.x, acc[4*i+0]);
                acc[4*i+1] = fmaf(pw, t.y, acc[4*i+1]);
                acc[4*i+2] = fmaf(pw, t.z, acc[4*i+2]);
                acc[4*i+3] = fmaf(pw, t.w, acc[4*i+3]);
            }
        }
    }

    const long ob = ((long)b * SQ + row) * HIDDEN + h * HEAD_DIM;
    __nv_bfloat16* hp = ohi + ob;
    __nv_bfloat16* lp = olo + ob;
    #pragma unroll
    for (int i = 0; i < 64; i += 8) {
        uint32_t ph[2], pl[2];
        #pragma unroll
        for (int j = 0; j < 2; j++) {
            __nv_bfloat162 th, tl;
            float a0 = acc[i + j * 2], a1 = acc[i + j * 2 + 1];
            th.x = __float2bfloat16(a0);
            th.y = __float2bfloat16(a1);
            tl.x = __float2bfloat16(a0 - __bfloat162float(th.x));
            tl.y = __float2bfloat16(a1 - __bfloat162float(th.y));
            ph[j] = *reinterpret_cast<uint32_t*>(&th);
            pl[j] = *reinterpret_cast<uint32_t*>(&tl);
        }
        uint32_t ph2[2], pl2[2];
        #pragma unroll
        for (int j = 0; j < 2; j++) {
            __nv_bfloat162 th, tl;
            float a0 = acc[i + 4 + j * 2], a1 = acc[i + 4 + j * 2 + 1];
            th.x = __float2bfloat16(a0);
            th.y = __float2bfloat16(a1);
            tl.x = __float2bfloat16(a0 - __bfloat162float(th.x));
            tl.y = __float2bfloat16(a1 - __bfloat162float(th.y));
            ph2[j] = *reinterpret_cast<uint32_t*>(&th);
            pl2[j] = *reinterpret_cast<uint32_t*>(&tl);
        }
        *(uint4*)(hp + i) = make_uint4(ph[0], ph[1], ph2[0], ph2[1]);
        *(uint4*)(lp + i) = make_uint4(pl[0], pl[1], pl2[0], pl2[1]);
    }
}

// ============================================================================
// Launcher
// ============================================================================
extern "C" void kernel_launch(void* const* d_in, const int* in_sizes, int n_in,
                              void* d_out, int out_size)
{
    const float* hidden = (const float*)d_in[0];
    const float* enc    = (const float*)d_in[1];
    const float* Wq     = (const float*)d_in[2];
    const float* Wk     = (const float*)d_in[3];
    const float* Wv     = (const float*)d_in[4];
    const float* Wk_ip  = (const float*)d_in[5];
    const float* Wv_ip  = (const float*)d_in[6];
    const float* Wout   = (const float*)d_in[7];
    const float* b_out  = (const float*)d_in[8];
    float* out = (float*)d_out;

    static bool attr_set = false;
    if (!attr_set) {
        cudaFuncSetAttribute(hmma_gemm, cudaFuncAttributeMaxDynamicSharedMemorySize, SMEM_TOT);
        attr_set = true;
    }

    __nv_bfloat16 *ahi, *alo, *ehi, *elo, *wqh, *wql, *wth, *wtl, *woh, *wol;
    float *q, *kv;
    cudaGetSymbolAddress((void**)&ahi, g_ahi);
    cudaGetSymbolAddress((void**)&alo, g_alo);
    cudaGetSymbolAddress((void**)&ehi, g_ehi);
    cudaGetSymbolAddress((void**)&elo, g_elo);
    cudaGetSymbolAddress((void**)&wqh, g_wqT_hi);
    cudaGetSymbolAddress((void**)&wql, g_wqT_lo);
    cudaGetSymbolAddress((void**)&wth, g_wT_hi);
    cudaGetSymbolAddress((void**)&wtl, g_wT_lo);
    cudaGetSymbolAddress((void**)&woh, g_woutT_hi);
    cudaGetSymbolAddress((void**)&wol, g_woutT_lo);
    cudaGetSymbolAddress((void**)&q,   g_q);
    cudaGetSymbolAddress((void**)&kv,  g_kv);

    const int M_big = NB * SQ;  // 16384
    const long WSLAB = (long)HIDDEN * CROSS;

    // 1) activation splits
    {
        int n4 = M_big * HIDDEN / 4;
        split_kernel<<<(n4 + 255) / 256, 256>>>(hidden, ahi, alo, n4);
    }
    {
        int n4 = NB * ENC * CROSS / 4;
        split_kernel<<<(n4 + 255) / 256, 256>>>(enc, ehi, elo, n4);
    }

    // 2) all weight transposes+splits in one launch
    {
        TSArgs t;
        t.src[0] = Wq;    t.dhi[0] = wqh;             t.dlo[0] = wql;             t.K[0] = HIDDEN;
        t.src[1] = Wk;    t.dhi[1] = wth + 0 * WSLAB; t.dlo[1] = wtl + 0 * WSLAB; t.K[1] = CROSS;
        t.src[2] = Wv;    t.dhi[2] = wth + 1 * WSLAB; t.dlo[2] = wtl + 1 * WSLAB; t.K[2] = CROSS;
        t.src[3] = Wk_ip; t.dhi[3] = wth + 2 * WSLAB; t.dlo[3] = wtl + 2 * WSLAB; t.K[3] = CROSS;
        t.src[4] = Wv_ip; t.dhi[4] = wth + 3 * WSLAB; t.dlo[4] = wtl + 3 * WSLAB; t.K[4] = CROSS;
        t.src[5] = Wout;  t.dhi[5] = woh;             t.dlo[5] = wol;             t.K[5] = HIDDEN;
        transpose_split_all<<<dim3(HIDDEN / 32, CROSS / 32, 6), dim3(32, 8)>>>(t);
    }

    // 3) Q = hidden @ Wq   (tiles: 5 x 128)
    {
        GemmArgs a = {ahi, alo, wqh, wql, q, 0, 0, M_big, HIDDEN, HIDDEN,
                      nullptr, nullptr, 0};
        hmma_gemm<<<dim3(HIDDEN / 256, M_big / 128, 1), 256, SMEM_TOT>>>(a);
    }

    // 4) merged K/V/ipK/ipV projections (grid.z = 16)
    {
        GemmArgs a = {ehi, elo, wth, wtl, kv, 0, 0, TXT, CROSS, HIDDEN,
                      nullptr, nullptr, 1};
        hmma_gemm<<<dim3(HIDDEN / 256, 1, 16), 256, SMEM_TOT>>>(a);
    }

    // 5) attention -> bf16 hi/lo
    attn_kernel<<<dim3(SQ / 128, NHEADS, NB), 128>>>(q, kv, ahi, alo);

    // 6) out = hs @ Wout + b_out + residual
    {
        GemmArgs a = {ahi, alo, woh, wol, out, 0, 0, M_big, HIDDEN, HIDDEN,
                      b_out, hidden, 0};
        hmma_gemm<<<dim3(HIDDEN / 256, M_big / 128, 1), 256, SMEM_TOT>>>(a);
    }
}

// round 6
// speedup vs baseline: 1.3243x; 1.3243x over previous
#include <cuda_runtime.h>
#include <cuda_bf16.h>
#include <cstdint>

#define NHEADS 20
#define HEAD_DIM 64
#define HIDDEN 1280
#define CROSS 2048
#define NB 4
#define SQ 4096
#define TXT 77
#define NTOK 4
#define ENC (TXT + NTOK)

// ============================================================================
// PTX helpers (baseline-family only: mma.sync / ldmatrix / cp.async)
// ============================================================================
__device__ __forceinline__ uint32_t smem_to_u32(const void* smem_ptr) {
    uint32_t addr;
    asm("{ .reg .u64 tmp; cvta.to.shared.u64 tmp, %1; cvt.u32.u64 %0, tmp; }"
        : "=r"(addr) : "l"(smem_ptr));
    return addr;
}

__device__ __forceinline__ void cp_async16(uint32_t dst, const void* src, int bytes) {
    asm volatile("cp.async.cg.shared.global [%0], [%1], 16, %2;"
                 :: "r"(dst), "l"(src), "r"(bytes));
}
#define CP_COMMIT() asm volatile("cp.async.commit_group;" ::: "memory")
#define CP_WAIT(N)  asm volatile("cp.async.wait_group %0;" :: "n"(N) : "memory")

__device__ __forceinline__ void ldsm_x4(uint32_t* r, uint32_t a) {
    asm volatile("ldmatrix.sync.aligned.m8n8.x4.shared.b16 {%0,%1,%2,%3}, [%4];"
                 : "=r"(r[0]), "=r"(r[1]), "=r"(r[2]), "=r"(r[3]) : "r"(a));
}

__device__ __forceinline__ void mma16816(float* c, const uint32_t* a,
                                         uint32_t b0, uint32_t b1) {
    asm volatile(
        "mma.sync.aligned.m16n8k16.row.col.f32.bf16.bf16.f32 "
        "{%0,%1,%2,%3},{%4,%5,%6,%7},{%8,%9},{%0,%1,%2,%3};"
        : "+f"(c[0]), "+f"(c[1]), "+f"(c[2]), "+f"(c[3])
        : "r"(a[0]), "r"(a[1]), "r"(a[2]), "r"(a[3]), "r"(b0), "r"(b1));
}

__device__ __forceinline__ uint32_t pack_bf16x2(float a, float b) {
    __nv_bfloat162 t;
    t.x = __float2bfloat16(a);
    t.y = __float2bfloat16(b);
    return *reinterpret_cast<uint32_t*>(&t);
}

// ============================================================================
// Scratch (static device allocations)
// ============================================================================
__device__ __nv_bfloat16 g_ahi[NB * SQ * HIDDEN];
__device__ __nv_bfloat16 g_alo[NB * SQ * HIDDEN];
__device__ __nv_bfloat16 g_qhi[NB * SQ * HIDDEN];
__device__ __nv_bfloat16 g_qlo[NB * SQ * HIDDEN];
__device__ __nv_bfloat16 g_ehi[NB * ENC * CROSS];
__device__ __nv_bfloat16 g_elo[NB * ENC * CROSS];
__device__ __nv_bfloat16 g_wqT_hi[HIDDEN * HIDDEN];
__device__ __nv_bfloat16 g_wqT_lo[HIDDEN * HIDDEN];
__device__ __nv_bfloat16 g_wT_hi[4 * HIDDEN * CROSS];
__device__ __nv_bfloat16 g_wT_lo[4 * HIDDEN * CROSS];
__device__ __nv_bfloat16 g_woutT_hi[HIDDEN * HIDDEN];
__device__ __nv_bfloat16 g_woutT_lo[HIDDEN * HIDDEN];
__device__ __nv_bfloat16 g_kvhi[4 * NB * TXT * HIDDEN];  // k,v,ipk,ipv
__device__ __nv_bfloat16 g_kvlo[4 * NB * TXT * HIDDEN];

// ============================================================================
// fp32 -> bf16 hi/lo split
// ============================================================================
__global__ __launch_bounds__(256)
void split_kernel(const float* __restrict__ in, __nv_bfloat16* __restrict__ hi,
                  __nv_bfloat16* __restrict__ lo, int n4)
{
    int i = blockIdx.x * blockDim.x + threadIdx.x;
    if (i >= n4) return;
    float4 x = ((const float4*)in)[i];
    __nv_bfloat16 h0 = __float2bfloat16(x.x);
    __nv_bfloat16 h1 = __float2bfloat16(x.y);
    __nv_bfloat16 h2 = __float2bfloat16(x.z);
    __nv_bfloat16 h3 = __float2bfloat16(x.w);
    __nv_bfloat162 hA; hA.x = h0; hA.y = h1;
    __nv_bfloat162 hB; hB.x = h2; hB.y = h3;
    ((__nv_bfloat162*)hi)[2 * i]     = hA;
    ((__nv_bfloat162*)hi)[2 * i + 1] = hB;
    __nv_bfloat162 lA;
    lA.x = __float2bfloat16(x.x - __bfloat162float(h0));
    lA.y = __float2bfloat16(x.y - __bfloat162float(h1));
    __nv_bfloat162 lB;
    lB.x = __float2bfloat16(x.z - __bfloat162float(h2));
    lB.y = __float2bfloat16(x.w - __bfloat162float(h3));
    ((__nv_bfloat162*)lo)[2 * i]     = lA;
    ((__nv_bfloat162*)lo)[2 * i + 1] = lB;
}

// ============================================================================
// Merged transpose + split of all 6 weights (grid.z selects weight).
// ============================================================================
struct TSArgs {
    const float* src[6];
    __nv_bfloat16* dhi[6];
    __nv_bfloat16* dlo[6];
    int K[6];
};

__global__ __launch_bounds__(256)
void transpose_split_all(TSArgs args)
{
    const int w = blockIdx.z;
    const int K = args.K[w];
    const int k0 = blockIdx.y * 32;
    if (k0 >= K) return;
    const float* in = args.src[w];
    __nv_bfloat16* ohi = args.dhi[w];
    __nv_bfloat16* olo = args.dlo[w];

    __shared__ float t[32][33];
    const int tx = threadIdx.x, ty = threadIdx.y;
    const int n0 = blockIdx.x * 32;
    #pragma unroll
    for (int j = ty; j < 32; j += 8)
        t[j][tx] = in[(long)(k0 + j) * HIDDEN + n0 + tx];
    __syncthreads();
    #pragma unroll
    for (int j = ty; j < 32; j += 8) {
        float x = t[tx][j];
        __nv_bfloat16 h = __float2bfloat16(x);
        long o = (long)(n0 + j) * K + k0 + tx;
        ohi[o] = h;
        olo[o] = __float2bfloat16(x - __bfloat162float(h));
    }
}

// ============================================================================
// HMMA GEMM (round-4 config restored): CTA 128x128x32, 8 warps, warp 32x64,
// cp.async double buffer, 3-term bf16 split, 2 CTAs/SM.
// Epilogue: fp32 (+bias+resid) OR bf16 hi/lo split out (Chi/Clo != null).
// ============================================================================
#define LDS_ROW 80
#define ABUF    10240
#define OFF_AHI 0
#define OFF_ALO 20480
#define OFF_BHI 40960
#define OFF_BLO 61440
#define SMEM_TOT 81920

struct GemmArgs {
    const __nv_bfloat16 *Ahi, *Alo, *Bhi, *Blo;
    float* C;
    __nv_bfloat16 *Chi, *Clo;
    long aBatch, cBatch;
    int Mvalid, K, ldc;
    const float *bias, *resid;
    int kvmode;
};

__device__ __forceinline__ void gemm_load_stage(
    uint32_t smb, int s, int tid, int rowBase, int colBase, int Mvalid, int K,
    const __nv_bfloat16* __restrict__ Ahi, const __nv_bfloat16* __restrict__ Alo,
    const __nv_bfloat16* __restrict__ Bhi, const __nv_bfloat16* __restrict__ Blo)
{
    const int b = s & 1;
    const long k0 = (long)s << 5;
    #pragma unroll
    for (int i = 0; i < 2; i++) {
        int idx = tid + i * 256;
        int r = idx >> 2, c = idx & 3;
        uint32_t d = smb + (uint32_t)(b * ABUF + r * LDS_ROW + c * 16);
        long go = ((long)(rowBase + r)) * K + k0 + c * 8;
        int bytes = (rowBase + r < Mvalid) ? 16 : 0;
        cp_async16(d + OFF_AHI, Ahi + go, bytes);
        cp_async16(d + OFF_ALO, Alo + go, bytes);
        long gb = ((long)(colBase + r)) * K + k0 + c * 8;
        cp_async16(d + OFF_BHI, Bhi + gb, 16);
        cp_async16(d + OFF_BLO, Blo + gb, 16);
    }
    CP_COMMIT();
}

__global__ __launch_bounds__(256, 2)
void hmma_gemm(GemmArgs args)
{
    extern __shared__ __align__(16) char smx[];
    const uint32_t smb = smem_to_u32(smx);
    const int tid = threadIdx.x;

    const __nv_bfloat16* Ahi = args.Ahi;
    const __nv_bfloat16* Alo = args.Alo;
    const __nv_bfloat16* Bhi = args.Bhi;
    const __nv_bfloat16* Blo = args.Blo;
    int Mvalid = args.Mvalid;
    const int K = args.K, ldc = args.ldc;
    long cOff = 0;

    if (args.kvmode) {
        const int gemm = blockIdx.z >> 2;
        const int batch = blockIdx.z & 3;
        const long aoff = (long)batch * ENC * CROSS + (gemm >= 2 ? (long)TXT * CROSS : 0);
        Ahi += aoff;  Alo += aoff;
        Bhi += (long)gemm * HIDDEN * CROSS;
        Blo += (long)gemm * HIDDEN * CROSS;
        cOff = ((long)gemm * NB + batch) * TXT * HIDDEN;
        Mvalid = (gemm < 2) ? TXT : NTOK;
    } else {
        Ahi += blockIdx.z * args.aBatch;
        Alo += blockIdx.z * args.aBatch;
        cOff = blockIdx.z * args.cBatch;
    }

    const int rowBase = blockIdx.y * 128;
    const int colBase = blockIdx.x * 128;
    const int NS = K >> 5;

    const int warp = tid >> 5, lane = tid & 31;
    const int wm = warp >> 1, wn = warp & 1;
    const int m0 = wm * 32, n0 = wn * 64;

    const uint32_t aoffs = (uint32_t)((m0 + (lane & 15)) * LDS_ROW + (lane >> 4) * 16);
    const uint32_t boffs = (uint32_t)((n0 + ((lane >> 4) & 1) * 8 + (lane & 7)) * LDS_ROW
                                      + ((lane >> 3) & 1) * 16);

    float acc[2][8][4];
    #pragma unroll
    for (int mi = 0; mi < 2; mi++)
        #pragma unroll
        for (int nj = 0; nj < 8; nj++)
            #pragma unroll
            for (int t = 0; t < 4; t++) acc[mi][nj][t] = 0.f;

    gemm_load_stage(smb, 0, tid, rowBase, colBase, Mvalid, K, Ahi, Alo, Bhi, Blo);

    for (int s = 0; s < NS; ++s) {
        if (s + 1 < NS) {
            gemm_load_stage(smb, s + 1, tid, rowBase, colBase, Mvalid, K, Ahi, Alo, Bhi, Blo);
            CP_WAIT(1);
        } else {
            CP_WAIT(0);
        }
        __syncthreads();

        const int b = s & 1;
        const uint32_t aHi = smb + OFF_AHI + b * ABUF;
        const uint32_t aLo = smb + OFF_ALO + b * ABUF;
        const uint32_t bHi = smb + OFF_BHI + b * ABUF;
        const uint32_t bLo = smb + OFF_BLO + b * ABUF;

        #pragma unroll
        for (int ks = 0; ks < 2; ks++) {
            uint32_t Ah[2][4], Al[2][4];
            #pragma unroll
            for (int mi = 0; mi < 2; mi++) {
                ldsm_x4(Ah[mi], aHi + aoffs + mi * 16 * LDS_ROW + ks * 32);
                ldsm_x4(Al[mi], aLo + aoffs + mi * 16 * LDS_ROW + ks * 32);
            }
            #pragma unroll
            for (int half = 0; half < 2; half++) {
                uint32_t Bh[2][4], Bl[2][4];
                #pragma unroll
                for (int nn = 0; nn < 2; nn++) {
                    const uint32_t bo = boffs + (half * 2 + nn) * 16 * LDS_ROW + ks * 32;
                    ldsm_x4(Bh[nn], bHi + bo);
                    ldsm_x4(Bl[nn], bLo + bo);
                }
                #pragma unroll
                for (int mi = 0; mi < 2; mi++) {
                    #pragma unroll
                    for (int j4 = 0; j4 < 4; j4++) {
                        const int ni = j4 >> 1, h = (j4 & 1) * 2;
                        float* a = acc[mi][half * 4 + j4];
                        mma16816(a, Ah[mi], Bh[ni][h], Bh[ni][h + 1]);
                        mma16816(a, Ah[mi], Bl[ni][h], Bl[ni][h + 1]);
                        mma16816(a, Al[mi], Bh[ni][h], Bh[ni][h + 1]);
                    }
                }
            }
        }
        __syncthreads();
    }

    // Epilogue
    const int g = lane >> 2, tig = lane & 3;
    const float* bias = args.bias;
    const float* resid = args.resid;
    #pragma unroll
    for (int mi = 0; mi < 2; mi++) {
        #pragma unroll
        for (int nj = 0; nj < 8; nj++) {
            const int r0 = rowBase + m0 + mi * 16 + g;
            const int col = colBase + n0 + nj * 8 + tig * 2;
            float2 v0 = make_float2(acc[mi][nj][0], acc[mi][nj][1]);
            float2 v1 = make_float2(acc[mi][nj][2], acc[mi][nj][3]);
            if (args.Chi) {
                // bf16 hi/lo split output
                if (r0 < Mvalid) {
                    long o = cOff + (long)r0 * ldc + col;
                    __nv_bfloat16 h0 = __float2bfloat16(v0.x);
                    __nv_bfloat16 h1 = __float2bfloat16(v0.y);
                    __nv_bfloat162 hh; hh.x = h0; hh.y = h1;
                    *(uint32_t*)(args.Chi + o) = *reinterpret_cast<uint32_t*>(&hh);
                    *(uint32_t*)(args.Clo + o) = pack_bf16x2(
                        v0.x - __bfloat162float(h0), v0.y - __bfloat162float(h1));
                }
                if (r0 + 8 < Mvalid) {
                    long o = cOff + (long)(r0 + 8) * ldc + col;
                    __nv_bfloat16 h0 = __float2bfloat16(v1.x);
                    __nv_bfloat16 h1 = __float2bfloat16(v1.y);
                    __nv_bfloat162 hh; hh.x = h0; hh.y = h1;
                    *(uint32_t*)(args.Chi + o) = *reinterpret_cast<uint32_t*>(&hh);
                    *(uint32_t*)(args.Clo + o) = pack_bf16x2(
                        v1.x - __bfloat162float(h0), v1.y - __bfloat162float(h1));
                }
            } else {
                float* C = args.C + cOff;
                if (bias) {
                    const float2 bi = *(const float2*)(bias + col);
                    v0.x += bi.x; v0.y += bi.y;
                    v1.x += bi.x; v1.y += bi.y;
                    if (r0 < Mvalid) {
                        const float2 rr = *(const float2*)(resid + (long)r0 * ldc + col);
                        v0.x += rr.x; v0.y += rr.y;
                    }
                    if (r0 + 8 < Mvalid) {
                        const float2 rr = *(const float2*)(resid + (long)(r0 + 8) * ldc + col);
                        v1.x += rr.x; v1.y += rr.y;
                    }
                }
                if (r0 < Mvalid)     *(float2*)(C + (long)r0 * ldc + col)       = v0;
                if (r0 + 8 < Mvalid) *(float2*)(C + (long)(r0 + 8) * ldc + col) = v1;
            }
        }
    }
}

// ============================================================================
// HMMA flash attention: CTA = 128 q-rows x 96 keys (77 text + pad + 4 ip @80).
// 8 warps, warp = 16 rows. 3-term bf16 split everywhere. V stored transposed.
// Writes hs as bf16 hi/lo split.
// ============================================================================
#define AROW 144
#define KROW 144
#define VROW 208
#define OFF_QHI 0
#define OFF_QLO (128 * AROW)                // 18432
#define OFF_KHI (2 * 128 * AROW)            // 36864
#define OFF_KLO (OFF_KHI + 96 * KROW)       // 50688
#define OFF_VHI (OFF_KLO + 96 * KROW)       // 64512
#define OFF_VLO (OFF_VHI + 64 * VROW)       // 77824
#define SMEM_ATTN (OFF_VLO + 64 * VROW)     // 91136

__global__ __launch_bounds__(256)
void attn_mma(const __nv_bfloat16* __restrict__ qhi,
              const __nv_bfloat16* __restrict__ qlo,
              const __nv_bfloat16* __restrict__ kvhi,
              const __nv_bfloat16* __restrict__ kvlo,
              __nv_bfloat16* __restrict__ ohi, __nv_bfloat16* __restrict__ olo)
{
    extern __shared__ __align__(16) char smx[];
    const uint32_t smb = smem_to_u32(smx);
    const int tid = threadIdx.x;
    const int b = blockIdx.z, h = blockIdx.y;
    const int rowBase = blockIdx.x * 128;
    const long SLAB = (long)NB * TXT * HIDDEN;   // per-gemm stride in kv

    // Q tile: 128 rows x 64 dims (hi+lo)
    #pragma unroll
    for (int i = 0; i < 4; i++) {
        int idx = tid + i * 256;
        int r = idx >> 3, c = idx & 7;
        long src = ((long)b * SQ + rowBase + r) * HIDDEN + h * 64 + c * 8;
        uint32_t d = smb + (uint32_t)(r * AROW + c * 16);
        cp_async16(d + OFF_QHI, qhi + src, 16);
        cp_async16(d + OFF_QLO, qlo + src, 16);
    }
    // K tile: 96 rows (0-76 text K, 80-83 ipK, rest zero)
    #pragma unroll
    for (int i = 0; i < 3; i++) {
        int idx = tid + i * 256;
        int r = idx >> 3, c = idx & 7;
        int bytes = 0;
        long src = 0;
        if (r < TXT) {
            bytes = 16;
            src = (long)b * TXT * HIDDEN + (long)r * HIDDEN + h * 64 + c * 8;
        } else if (r >= 80 && r < 80 + NTOK) {
            bytes = 16;
            src = 2 * SLAB + (long)b * TXT * HIDDEN + (long)(r - 80) * HIDDEN + h * 64 + c * 8;
        }
        uint32_t d = smb + OFF_KHI + (uint32_t)(r * KROW + c * 16);
        cp_async16(d, kvhi + src, bytes);
        cp_async16(d + (OFF_KLO - OFF_KHI), kvlo + src, bytes);
    }
    CP_COMMIT();

    // V transposed (scalar): VT[dim][key], 64 x 96
    for (int idx = tid; idx < 96 * 64; idx += 256) {
        int key = idx >> 6, dim = idx & 63;
        __nv_bfloat16 vh = __float2bfloat16(0.f), vl = vh;
        if (key < TXT) {
            long src = SLAB + (long)b * TXT * HIDDEN + (long)key * HIDDEN + h * 64 + dim;
            vh = kvhi[src]; vl = kvlo[src];
        } else if (key >= 80 && key < 80 + NTOK) {
            long src = 3 * SLAB + (long)b * TXT * HIDDEN + (long)(key - 80) * HIDDEN + h * 64 + dim;
            vh = kvhi[src]; vl = kvlo[src];
        }
        *(__nv_bfloat16*)(smx + OFF_VHI + dim * VROW + key * 2) = vh;
        *(__nv_bfloat16*)(smx + OFF_VLO + dim * VROW + key * 2) = vl;
    }
    CP_WAIT(0);
    __syncthreads();

    const int warp = tid >> 5, lane = tid & 31;
    const int m0 = warp * 16;
    const int tig = lane & 3;
    const uint32_t aoffs = smb + (uint32_t)((m0 + (lane & 15)) * AROW + (lane >> 4) * 16);
    const uint32_t kbase = smb + OFF_KHI
        + (uint32_t)((((lane >> 4) & 1) * 8 + (lane & 7)) * KROW + ((lane >> 3) & 1) * 16);

    // S = Q K^T (12 n-tiles of 8 keys = 96)
    float s[12][4];
    #pragma unroll
    for (int j = 0; j < 12; j++)
        #pragma unroll
        for (int e = 0; e < 4; e++) s[j][e] = 0.f;

    #pragma unroll
    for (int ks = 0; ks < 4; ks++) {
        uint32_t Qh[4], Ql[4];
        ldsm_x4(Qh, aoffs + ks * 32);
        ldsm_x4(Ql, aoffs + OFF_QLO + ks * 32);
        #pragma unroll
        for (int t = 0; t < 6; t++) {
            uint32_t Bh[4], Bl[4];
            ldsm_x4(Bh, kbase + t * 16 * KROW + ks * 32);
            ldsm_x4(Bl, kbase + (OFF_KLO - OFF_KHI) + t * 16 * KROW + ks * 32);
            #pragma unroll
            for (int half = 0; half < 2; half++) {
                const int j = 2 * t + half, hh = half * 2;
                mma16816(s[j], Qh, Bh[hh], Bh[hh + 1]);
                mma16816(s[j], Qh, Bl[hh], Bl[hh + 1]);
                mma16816(s[j], Ql, Bh[hh], Bh[hh + 1]);
            }
        }
    }

    // scale + mask
    const bool ipOn = (b & 1);
    float mx[2]  = {-1e30f, -1e30f};
    float mx2[2] = {-1e30f, -1e30f};
    #pragma unroll
    for (int j = 0; j < 10; j++)
        #pragma unroll
        for (int e = 0; e < 4; e++) {
            int col = j * 8 + tig * 2 + (e & 1);
            float v = s[j][e] * 0.125f;
            s[j][e] = (col < TXT) ? v : -1e30f;
            mx[e >> 1] = fmaxf(mx[e >> 1], s[j][e]);
        }
    #pragma unroll
    for (int j = 10; j < 12; j++)
        #pragma unroll
        for (int e = 0; e < 4; e++) {
            int col = j * 8 + tig * 2 + (e & 1);
            float v = s[j][e] * 0.125f;
            s[j][e] = (col >= 80 && col < 80 + NTOK) ? v : -1e30f;
            mx2[e >> 1] = fmaxf(mx2[e >> 1], s[j][e]);
        }
    #pragma unroll
    for (int off = 1; off <= 2; off <<= 1) {
        mx[0]  = fmaxf(mx[0],  __shfl_xor_sync(0xffffffffu, mx[0],  off));
        mx[1]  = fmaxf(mx[1],  __shfl_xor_sync(0xffffffffu, mx[1],  off));
        mx2[0] = fmaxf(mx2[0], __shfl_xor_sync(0xffffffffu, mx2[0], off));
        mx2[1] = fmaxf(mx2[1], __shfl_xor_sync(0xffffffffu, mx2[1], off));
    }
    float l[2] = {0.f, 0.f}, l2[2] = {0.f, 0.f};
    #pragma unroll
    for (int j = 0; j < 10; j++)
        #pragma unroll
        for (int e = 0; e < 4; e++) {
            float p = __expf(s[j][e] - mx[e >> 1]);
            s[j][e] = p;
            l[e >> 1] += p;
        }
    #pragma unroll
    for (int j = 10; j < 12; j++)
        #pragma unroll
        for (int e = 0; e < 4; e++) {
            float p = __expf(s[j][e] - mx2[e >> 1]);
            s[j][e] = p;
            l2[e >> 1] += p;
        }
    #pragma unroll
    for (int off = 1; off <= 2; off <<= 1) {
        l[0]  += __shfl_xor_sync(0xffffffffu, l[0],  off);
        l[1]  += __shfl_xor_sync(0xffffffffu, l[1],  off);
        l2[0] += __shfl_xor_sync(0xffffffffu, l2[0], off);
        l2[1] += __shfl_xor_sync(0xffffffffu, l2[1], off);
    }
    float inv[2], inv2[2];
    inv[0] = 1.f / l[0];
    inv[1] = 1.f / l[1];
    inv2[0] = ipOn ? 1.f / l2[0] : 0.f;
    inv2[1] = ipOn ? 1.f / l2[1] : 0.f;
    #pragma unroll
    for (int j = 0; j < 10; j++)
        #pragma unroll
        for (int e = 0; e < 4; e++) s[j][e] *= inv[e >> 1];
    #pragma unroll
    for (int j = 10; j < 12; j++)
        #pragma unroll
        for (int e = 0; e < 4; e++) s[j][e] *= inv2[e >> 1];

    // PV: out[8 dim-tiles][4]
    const uint32_t vbase = smb + OFF_VHI
        + (uint32_t)((((lane >> 4) & 1) * 8 + (lane & 7)) * VROW + ((lane >> 3) & 1) * 16);
    float out[8][4];
    #pragma unroll
    for (int d = 0; d < 8; d++)
        #pragma unroll
        for (int e = 0; e < 4; e++) out[d][e] = 0.f;

    #pragma unroll
    for (int kk = 0; kk < 6; kk++) {
        uint32_t ah[4], al[4];
        #pragma unroll
        for (int r = 0; r < 4; r++) {
            const int t = 2 * kk + (r >> 1);
            const int pi = (r & 1) * 2;
            float v0 = s[t][pi], v1 = s[t][pi + 1];
            __nv_bfloat16 h0 = __float2bfloat16(v0);
            __nv_bfloat16 h1 = __float2bfloat16(v1);
            __nv_bfloat162 hh; hh.x = h0; hh.y = h1;
            ah[r] = *reinterpret_cast<uint32_t*>(&hh);
            al[r] = pack_bf16x2(v0 - __bfloat162float(h0), v1 - __bfloat162float(h1));
        }
        #pragma unroll
        for (int d = 0; d < 4; d++) {
            uint32_t Vh[4], Vl[4];
            ldsm_x4(Vh, vbase + d * 16 * VROW + kk * 32);
            ldsm_x4(Vl, vbase + (OFF_VLO - OFF_VHI) + d * 16 * VROW + kk * 32);
            #pragma unroll
            for (int half = 0; half < 2; half++) {
                const int j = 2 * d + half, hh = half * 2;
                mma16816(out[j], ah, Vh[hh], Vh[hh + 1]);
                mma16816(out[j], ah, Vl[hh], Vl[hh + 1]);
                mma16816(out[j], al, Vh[hh], Vh[hh + 1]);
            }
        }
    }

    // write hs bf16 hi/lo split
    const int g = lane >> 2;
    const long row0 = (long)b * SQ + rowBase + m0 + g;
    #pragma unroll
    for (int d = 0; d < 8; d++) {
        const int col = h * 64 + d * 8 + tig * 2;
        #pragma unroll
        for (int rr = 0; rr < 2; rr++) {
            float v0 = out[d][rr * 2 + 0], v1 = out[d][rr * 2 + 1];
            long o = (row0 + rr * 8) * HIDDEN + col;
            __nv_bfloat16 h0 = __float2bfloat16(v0);
            __nv_bfloat16 h1 = __float2bfloat16(v1);
            __nv_bfloat162 hh; hh.x = h0; hh.y = h1;
            *(uint32_t*)(ohi + o) = *reinterpret_cast<uint32_t*>(&hh);
            *(uint32_t*)(olo + o) = pack_bf16x2(
                v0 - __bfloat162float(h0), v1 - __bfloat162float(h1));
        }
    }
}

// ============================================================================
// Launcher
// ============================================================================
extern "C" void kernel_launch(void* const* d_in, const int* in_sizes, int n_in,
                              void* d_out, int out_size)
{
    const float* hidden = (const float*)d_in[0];
    const float* enc    = (const float*)d_in[1];
    const float* Wq     = (const float*)d_in[2];
    const float* Wk     = (const float*)d_in[3];
    const float* Wv     = (const float*)d_in[4];
    const float* Wk_ip  = (const float*)d_in[5];
    const float* Wv_ip  = (const float*)d_in[6];
    const float* Wout   = (const float*)d_in[7];
    const float* b_out  = (const float*)d_in[8];
    float* out = (float*)d_out;

    static bool attr_set = false;
    if (!attr_set) {
        cudaFuncSetAttribute(hmma_gemm, cudaFuncAttributeMaxDynamicSharedMemorySize, SMEM_TOT);
        cudaFuncSetAttribute(attn_mma, cudaFuncAttributeMaxDynamicSharedMemorySize, SMEM_ATTN);
        attr_set = true;
    }

    __nv_bfloat16 *ahi, *alo, *qhi, *qlo, *ehi, *elo;
    __nv_bfloat16 *wqh, *wql, *wth, *wtl, *woh, *wol, *kvh, *kvl;
    cudaGetSymbolAddress((void**)&ahi, g_ahi);
    cudaGetSymbolAddress((void**)&alo, g_alo);
    cudaGetSymbolAddress((void**)&qhi, g_qhi);
    cudaGetSymbolAddress((void**)&qlo, g_qlo);
    cudaGetSymbolAddress((void**)&ehi, g_ehi);
    cudaGetSymbolAddress((void**)&elo, g_elo);
    cudaGetSymbolAddress((void**)&wqh, g_wqT_hi);
    cudaGetSymbolAddress((void**)&wql, g_wqT_lo);
    cudaGetSymbolAddress((void**)&wth, g_wT_hi);
    cudaGetSymbolAddress((void**)&wtl, g_wT_lo);
    cudaGetSymbolAddress((void**)&woh, g_woutT_hi);
    cudaGetSymbolAddress((void**)&wol, g_woutT_lo);
    cudaGetSymbolAddress((void**)&kvh, g_kvhi);
    cudaGetSymbolAddress((void**)&kvl, g_kvlo);

    const int M_big = NB * SQ;  // 16384
    const long WSLAB = (long)HIDDEN * CROSS;

    // 1) activation splits
    {
        int n4 = M_big * HIDDEN / 4;
        split_kernel<<<(n4 + 255) / 256, 256>>>(hidden, ahi, alo, n4);
    }
    {
        int n4 = NB * ENC * CROSS / 4;
        split_kernel<<<(n4 + 255) / 256, 256>>>(enc, ehi, elo, n4);
    }

    // 2) all weight transposes+splits in one launch
    {
        TSArgs t;
        t.src[0] = Wq;    t.dhi[0] = wqh;             t.dlo[0] = wql;             t.K[0] = HIDDEN;
        t.src[1] = Wk;    t.dhi[1] = wth + 0 * WSLAB; t.dlo[1] = wtl + 0 * WSLAB; t.K[1] = CROSS;
        t.src[2] = Wv;    t.dhi[2] = wth + 1 * WSLAB; t.dlo[2] = wtl + 1 * WSLAB; t.K[2] = CROSS;
        t.src[3] = Wk_ip; t.dhi[3] = wth + 2 * WSLAB; t.dlo[3] = wtl + 2 * WSLAB; t.K[3] = CROSS;
        t.src[4] = Wv_ip; t.dhi[4] = wth + 3 * WSLAB; t.dlo[4] = wtl + 3 * WSLAB; t.K[4] = CROSS;
        t.src[5] = Wout;  t.dhi[5] = woh;             t.dlo[5] = wol;             t.K[5] = HIDDEN;
        transpose_split_all<<<dim3(HIDDEN / 32, CROSS / 32, 6), dim3(32, 8)>>>(t);
    }

    // 3) Q = hidden @ Wq  -> bf16 hi/lo split
    {
        GemmArgs a = {ahi, alo, wqh, wql, nullptr, qhi, qlo,
                      0, 0, M_big, HIDDEN, HIDDEN, nullptr, nullptr, 0};
        hmma_gemm<<<dim3(HIDDEN / 128, M_big / 128, 1), 256, SMEM_TOT>>>(a);
    }

    // 4) merged K/V/ipK/ipV projections -> bf16 hi/lo split (grid.z = 16)
    {
        GemmArgs a = {ehi, elo, wth, wtl, nullptr, kvh, kvl,
                      0, 0, TXT, CROSS, HIDDEN, nullptr, nullptr, 1};
        hmma_gemm<<<dim3(HIDDEN / 128, 1, 16), 256, SMEM_TOT>>>(a);
    }

    // 5) HMMA attention -> hs bf16 hi/lo (reuses ahi/alo)
    attn_mma<<<dim3(SQ / 128, NHEADS, NB), 256, SMEM_ATTN>>>(qhi, qlo, kvh, kvl, ahi, alo);

    // 6) out = hs @ Wout + b_out + residual (fp32)
    {
        GemmArgs a = {ahi, alo, woh, wol, out, nullptr, nullptr,
                      0, 0, M_big, HIDDEN, HIDDEN, b_out, hidden, 0};
        hmma_gemm<<<dim3(HIDDEN / 128, M_big / 128, 1), 256, SMEM_TOT>>>(a);
    }
}

// round 7
// speedup vs baseline: 1.4979x; 1.1311x over previous
#include <cuda_runtime.h>
#include <cuda_bf16.h>
#include <cstdint>

#define NHEADS 20
#define HEAD_DIM 64
#define HIDDEN 1280
#define CROSS 2048
#define NB 4
#define SQ 4096
#define TXT 77
#define NTOK 4
#define ENC (TXT + NTOK)

// ============================================================================
// PTX helpers (baseline-family only: mma.sync / ldmatrix / cp.async)
// ============================================================================
__device__ __forceinline__ uint32_t smem_to_u32(const void* smem_ptr) {
    uint32_t addr;
    asm("{ .reg .u64 tmp; cvta.to.shared.u64 tmp, %1; cvt.u32.u64 %0, tmp; }"
        : "=r"(addr) : "l"(smem_ptr));
    return addr;
}

__device__ __forceinline__ void cp_async16(uint32_t dst, const void* src, int bytes) {
    asm volatile("cp.async.cg.shared.global [%0], [%1], 16, %2;"
                 :: "r"(dst), "l"(src), "r"(bytes));
}
#define CP_COMMIT() asm volatile("cp.async.commit_group;" ::: "memory")
#define CP_WAIT(N)  asm volatile("cp.async.wait_group %0;" :: "n"(N) : "memory")

__device__ __forceinline__ void ldsm_x4(uint32_t* r, uint32_t a) {
    asm volatile("ldmatrix.sync.aligned.m8n8.x4.shared.b16 {%0,%1,%2,%3}, [%4];"
                 : "=r"(r[0]), "=r"(r[1]), "=r"(r[2]), "=r"(r[3]) : "r"(a));
}

__device__ __forceinline__ void ldsm_x4_t(uint32_t* r, uint32_t a) {
    asm volatile("ldmatrix.sync.aligned.m8n8.x4.trans.shared.b16 {%0,%1,%2,%3}, [%4];"
                 : "=r"(r[0]), "=r"(r[1]), "=r"(r[2]), "=r"(r[3]) : "r"(a));
}

__device__ __forceinline__ void mma16816(float* c, const uint32_t* a,
                                         uint32_t b0, uint32_t b1) {
    asm volatile(
        "mma.sync.aligned.m16n8k16.row.col.f32.bf16.bf16.f32 "
        "{%0,%1,%2,%3},{%4,%5,%6,%7},{%8,%9},{%0,%1,%2,%3};"
        : "+f"(c[0]), "+f"(c[1]), "+f"(c[2]), "+f"(c[3])
        : "r"(a[0]), "r"(a[1]), "r"(a[2]), "r"(a[3]), "r"(b0), "r"(b1));
}

__device__ __forceinline__ uint32_t pack_bf16x2(float a, float b) {
    __nv_bfloat162 t;
    t.x = __float2bfloat16(a);
    t.y = __float2bfloat16(b);
    return *reinterpret_cast<uint32_t*>(&t);
}

// ============================================================================
// Scratch (static device allocations)
// ============================================================================
#define PART_STRIDE ((long)16 * TXT * HIDDEN)   // floats per split-K partial

__device__ __nv_bfloat16 g_ahi[NB * SQ * HIDDEN];
__device__ __nv_bfloat16 g_alo[NB * SQ * HIDDEN];
__device__ __nv_bfloat16 g_qhi[NB * SQ * HIDDEN];
__device__ __nv_bfloat16 g_qlo[NB * SQ * HIDDEN];
__device__ __nv_bfloat16 g_ehi[NB * ENC * CROSS];
__device__ __nv_bfloat16 g_elo[NB * ENC * CROSS];
__device__ __nv_bfloat16 g_wqT_hi[HIDDEN * HIDDEN];
__device__ __nv_bfloat16 g_wqT_lo[HIDDEN * HIDDEN];
__device__ __nv_bfloat16 g_wT_hi[4 * HIDDEN * CROSS];
__device__ __nv_bfloat16 g_wT_lo[4 * HIDDEN * CROSS];
__device__ __nv_bfloat16 g_woutT_hi[HIDDEN * HIDDEN];
__device__ __nv_bfloat16 g_woutT_lo[HIDDEN * HIDDEN];
__device__ __nv_bfloat16 g_kvhi[4 * NB * TXT * HIDDEN];  // k,v,ipk,ipv
__device__ __nv_bfloat16 g_kvlo[4 * NB * TXT * HIDDEN];
__device__ float g_part[8 * 16 * TXT * HIDDEN];          // split-K partials

// ============================================================================
// fp32 -> bf16 hi/lo split
// ============================================================================
__global__ __launch_bounds__(256)
void split_kernel(const float* __restrict__ in, __nv_bfloat16* __restrict__ hi,
                  __nv_bfloat16* __restrict__ lo, int n4)
{
    int i = blockIdx.x * blockDim.x + threadIdx.x;
    if (i >= n4) return;
    float4 x = ((const float4*)in)[i];
    __nv_bfloat16 h0 = __float2bfloat16(x.x);
    __nv_bfloat16 h1 = __float2bfloat16(x.y);
    __nv_bfloat16 h2 = __float2bfloat16(x.z);
    __nv_bfloat16 h3 = __float2bfloat16(x.w);
    __nv_bfloat162 hA; hA.x = h0; hA.y = h1;
    __nv_bfloat162 hB; hB.x = h2; hB.y = h3;
    ((__nv_bfloat162*)hi)[2 * i]     = hA;
    ((__nv_bfloat162*)hi)[2 * i + 1] = hB;
    __nv_bfloat162 lA;
    lA.x = __float2bfloat16(x.x - __bfloat162float(h0));
    lA.y = __float2bfloat16(x.y - __bfloat162float(h1));
    __nv_bfloat162 lB;
    lB.x = __float2bfloat16(x.z - __bfloat162float(h2));
    lB.y = __float2bfloat16(x.w - __bfloat162float(h3));
    ((__nv_bfloat162*)lo)[2 * i]     = lA;
    ((__nv_bfloat162*)lo)[2 * i + 1] = lB;
}

// ============================================================================
// Merged transpose + split of all 6 weights (grid.z selects weight).
// ============================================================================
struct TSArgs {
    const float* src[6];
    __nv_bfloat16* dhi[6];
    __nv_bfloat16* dlo[6];
    int K[6];
};

__global__ __launch_bounds__(256)
void transpose_split_all(TSArgs args)
{
    const int w = blockIdx.z;
    const int K = args.K[w];
    const int k0 = blockIdx.y * 32;
    if (k0 >= K) return;
    const float* in = args.src[w];
    __nv_bfloat16* ohi = args.dhi[w];
    __nv_bfloat16* olo = args.dlo[w];

    __shared__ float t[32][33];
    const int tx = threadIdx.x, ty = threadIdx.y;
    const int n0 = blockIdx.x * 32;
    #pragma unroll
    for (int j = ty; j < 32; j += 8)
        t[j][tx] = in[(long)(k0 + j) * HIDDEN + n0 + tx];
    __syncthreads();
    #pragma unroll
    for (int j = ty; j < 32; j += 8) {
        float x = t[tx][j];
        __nv_bfloat16 h = __float2bfloat16(x);
        long o = (long)(n0 + j) * K + k0 + tx;
        ohi[o] = h;
        olo[o] = __float2bfloat16(x - __bfloat162float(h));
    }
}

// ============================================================================
// HMMA GEMM (round-4/6 config): CTA 128x128x32, 8 warps, warp 32x64,
// cp.async double buffer, 3-term bf16 split, 2 CTAs/SM.
// Epilogue: fp32 (+bias+resid) OR bf16 hi/lo split out (Chi/Clo != null).
// ============================================================================
#define LDS_ROW 80
#define ABUF    10240
#define OFF_AHI 0
#define OFF_ALO 20480
#define OFF_BHI 40960
#define OFF_BLO 61440
#define SMEM_TOT 81920

struct GemmArgs {
    const __nv_bfloat16 *Ahi, *Alo, *Bhi, *Blo;
    float* C;
    __nv_bfloat16 *Chi, *Clo;
    int Mvalid, K, ldc;
    const float *bias, *resid;
};

__device__ __forceinline__ void gemm_load_stage(
    uint32_t smb, int s, int tid, int rowBase, int colBase, int Mvalid, int K,
    const __nv_bfloat16* __restrict__ Ahi, const __nv_bfloat16* __restrict__ Alo,
    const __nv_bfloat16* __restrict__ Bhi, const __nv_bfloat16* __restrict__ Blo)
{
    const int b = s & 1;
    const long k0 = (long)s << 5;
    #pragma unroll
    for (int i = 0; i < 2; i++) {
        int idx = tid + i * 256;
        int r = idx >> 2, c = idx & 3;
        uint32_t d = smb + (uint32_t)(b * ABUF + r * LDS_ROW + c * 16);
        long go = ((long)(rowBase + r)) * K + k0 + c * 8;
        int bytes = (rowBase + r < Mvalid) ? 16 : 0;
        cp_async16(d + OFF_AHI, Ahi + go, bytes);
        cp_async16(d + OFF_ALO, Alo + go, bytes);
        long gb = ((long)(colBase + r)) * K + k0 + c * 8;
        cp_async16(d + OFF_BHI, Bhi + gb, 16);
        cp_async16(d + OFF_BLO, Blo + gb, 16);
    }
    CP_COMMIT();
}

__global__ __launch_bounds__(256, 2)
void hmma_gemm(GemmArgs args)
{
    extern __shared__ __align__(16) char smx[];
    const uint32_t smb = smem_to_u32(smx);
    const int tid = threadIdx.x;

    const __nv_bfloat16* Ahi = args.Ahi;
    const __nv_bfloat16* Alo = args.Alo;
    const __nv_bfloat16* Bhi = args.Bhi;
    const __nv_bfloat16* Blo = args.Blo;
    const int Mvalid = args.Mvalid;
    const int K = args.K, ldc = args.ldc;

    const int rowBase = blockIdx.y * 128;
    const int colBase = blockIdx.x * 128;
    const int NS = K >> 5;

    const int warp = tid >> 5, lane = tid & 31;
    const int wm = warp >> 1, wn = warp & 1;
    const int m0 = wm * 32, n0 = wn * 64;

    const uint32_t aoffs = (uint32_t)((m0 + (lane & 15)) * LDS_ROW + (lane >> 4) * 16);
    const uint32_t boffs = (uint32_t)((n0 + ((lane >> 4) & 1) * 8 + (lane & 7)) * LDS_ROW
                                      + ((lane >> 3) & 1) * 16);

    float acc[2][8][4];
    #pragma unroll
    for (int mi = 0; mi < 2; mi++)
        #pragma unroll
        for (int nj = 0; nj < 8; nj++)
            #pragma unroll
            for (int t = 0; t < 4; t++) acc[mi][nj][t] = 0.f;

    gemm_load_stage(smb, 0, tid, rowBase, colBase, Mvalid, K, Ahi, Alo, Bhi, Blo);

    for (int s = 0; s < NS; ++s) {
        if (s + 1 < NS) {
            gemm_load_stage(smb, s + 1, tid, rowBase, colBase, Mvalid, K, Ahi, Alo, Bhi, Blo);
            CP_WAIT(1);
        } else {
            CP_WAIT(0);
        }
        __syncthreads();

        const int b = s & 1;
        const uint32_t aHi = smb + OFF_AHI + b * ABUF;
        const uint32_t aLo = smb + OFF_ALO + b * ABUF;
        const uint32_t bHi = smb + OFF_BHI + b * ABUF;
        const uint32_t bLo = smb + OFF_BLO + b * ABUF;

        #pragma unroll
        for (int ks = 0; ks < 2; ks++) {
            uint32_t Ah[2][4], Al[2][4];
            #pragma unroll
            for (int mi = 0; mi < 2; mi++) {
                ldsm_x4(Ah[mi], aHi + aoffs + mi * 16 * LDS_ROW + ks * 32);
                ldsm_x4(Al[mi], aLo + aoffs + mi * 16 * LDS_ROW + ks * 32);
            }
            #pragma unroll
            for (int half = 0; half < 2; half++) {
                uint32_t Bh[2][4], Bl[2][4];
                #pragma unroll
                for (int nn = 0; nn < 2; nn++) {
                    const uint32_t bo = boffs + (half * 2 + nn) * 16 * LDS_ROW + ks * 32;
                    ldsm_x4(Bh[nn], bHi + bo);
                    ldsm_x4(Bl[nn], bLo + bo);
                }
                #pragma unroll
                for (int mi = 0; mi < 2; mi++) {
                    #pragma unroll
                    for (int j4 = 0; j4 < 4; j4++) {
                        const int ni = j4 >> 1, h = (j4 & 1) * 2;
                        float* a = acc[mi][half * 4 + j4];
                        mma16816(a, Ah[mi], Bh[ni][h], Bh[ni][h + 1]);
                        mma16816(a, Ah[mi], Bl[ni][h], Bl[ni][h + 1]);
                        mma16816(a, Al[mi], Bh[ni][h], Bh[ni][h + 1]);
                    }
                }
            }
        }
        __syncthreads();
    }

    // Epilogue
    const int g = lane >> 2, tig = lane & 3;
    const float* bias = args.bias;
    const float* resid = args.resid;
    #pragma unroll
    for (int mi = 0; mi < 2; mi++) {
        #pragma unroll
        for (int nj = 0; nj < 8; nj++) {
            const int r0 = rowBase + m0 + mi * 16 + g;
            const int col = colBase + n0 + nj * 8 + tig * 2;
            float2 v0 = make_float2(acc[mi][nj][0], acc[mi][nj][1]);
            float2 v1 = make_float2(acc[mi][nj][2], acc[mi][nj][3]);
            if (args.Chi) {
                if (r0 < Mvalid) {
                    long o = (long)r0 * ldc + col;
                    __nv_bfloat16 h0 = __float2bfloat16(v0.x);
                    __nv_bfloat16 h1 = __float2bfloat16(v0.y);
                    __nv_bfloat162 hh; hh.x = h0; hh.y = h1;
                    *(uint32_t*)(args.Chi + o) = *reinterpret_cast<uint32_t*>(&hh);
                    *(uint32_t*)(args.Clo + o) = pack_bf16x2(
                        v0.x - __bfloat162float(h0), v0.y - __bfloat162float(h1));
                }
                if (r0 + 8 < Mvalid) {
                    long o = (long)(r0 + 8) * ldc + col;
                    __nv_bfloat16 h0 = __float2bfloat16(v1.x);
                    __nv_bfloat16 h1 = __float2bfloat16(v1.y);
                    __nv_bfloat162 hh; hh.x = h0; hh.y = h1;
                    *(uint32_t*)(args.Chi + o) = *reinterpret_cast<uint32_t*>(&hh);
                    *(uint32_t*)(args.Clo + o) = pack_bf16x2(
                        v1.x - __bfloat162float(h0), v1.y - __bfloat162float(h1));
                }
            } else {
                float* C = args.C;
                if (bias) {
                    const float2 bi = *(const float2*)(bias + col);
                    v0.x += bi.x; v0.y += bi.y;
                    v1.x += bi.x; v1.y += bi.y;
                    if (r0 < Mvalid) {
                        const float2 rr = *(const float2*)(resid + (long)r0 * ldc + col);
                        v0.x += rr.x; v0.y += rr.y;
                    }
                    if (r0 + 8 < Mvalid) {
                        const float2 rr = *(const float2*)(resid + (long)(r0 + 8) * ldc + col);
                        v1.x += rr.x; v1.y += rr.y;
                    }
                }
                if (r0 < Mvalid)     *(float2*)(C + (long)r0 * ldc + col)       = v0;
                if (r0 + 8 < Mvalid) *(float2*)(C + (long)(r0 + 8) * ldc + col) = v1;
            }
        }
    }
}

// ============================================================================
// Packed split-K kv projection GEMM.
// 8 M-tiles: parts 0-2 = text K (308 packed rows), 3-5 = text V,
//            6 = ipK (16 packed rows), 7 = ipV.
// grid (10, 8, 8): x = N-tile, y = part, z = K-split (256 K each, 8 stages).
// Writes fp32 partials; reduce_split_kv sums + hi/lo splits.
// ============================================================================
__device__ __forceinline__ bool kv_map(int part, int r, long& aRow, long& cRow)
{
    aRow = 0; cRow = 0;
    if (part < 6) {
        int R = (part % 3) * 128 + r;
        if (R >= 4 * TXT) return false;
        int batch = R / TXT, rr = R - batch * TXT;
        aRow = (long)batch * ENC + rr;
        cRow = (long)(((part < 3 ? 0 : 1) * 4 + batch) * TXT + rr);
        return true;
    } else {
        if (r >= 16) return false;
        int batch = r >> 2, rr = r & 3;
        aRow = (long)batch * ENC + TXT + rr;
        cRow = (long)(((part == 6 ? 2 : 3) * 4 + batch) * TXT + rr);
        return true;
    }
}

__device__ __forceinline__ void kv_load_stage(
    uint32_t smb, int s, int tid, int part, int colBase, int kBase,
    const __nv_bfloat16* __restrict__ ehi, const __nv_bfloat16* __restrict__ elo,
    const __nv_bfloat16* __restrict__ Bhi, const __nv_bfloat16* __restrict__ Blo)
{
    const int b = s & 1;
    const int k0 = kBase + (s << 5);
    #pragma unroll
    for (int i = 0; i < 2; i++) {
        int idx = tid + i * 256;
        int r = idx >> 2, c = idx & 3;
        long aRow, cRow;
        bool valid = kv_map(part, r, aRow, cRow);
        uint32_t d = smb + (uint32_t)(b * ABUF + r * LDS_ROW + c * 16);
        long go = aRow * CROSS + k0 + c * 8;
        int bytes = valid ? 16 : 0;
        cp_async16(d + OFF_AHI, ehi + go, bytes);
        cp_async16(d + OFF_ALO, elo + go, bytes);
        long gb = (long)(colBase + r) * CROSS + k0 + c * 8;
        cp_async16(d + OFF_BHI, Bhi + gb, 16);
        cp_async16(d + OFF_BLO, Blo + gb, 16);
    }
    CP_COMMIT();
}

__global__ __launch_bounds__(256, 2)
void hmma_gemm_kv(const __nv_bfloat16* __restrict__ ehi,
                  const __nv_bfloat16* __restrict__ elo,
                  const __nv_bfloat16* __restrict__ wth,
                  const __nv_bfloat16* __restrict__ wtl,
                  float* __restrict__ pbuf)
{
    extern __shared__ __align__(16) char smx[];
    const uint32_t smb = smem_to_u32(smx);
    const int tid = threadIdx.x;
    const int part = blockIdx.y;
    const int split = blockIdx.z;
    const int colBase = blockIdx.x * 128;
    const int gemm = part < 3 ? 0 : (part < 6 ? 1 : (part == 6 ? 2 : 3));
    const __nv_bfloat16* Bhi = wth + (long)gemm * HIDDEN * CROSS;
    const __nv_bfloat16* Blo = wtl + (long)gemm * HIDDEN * CROSS;
    const int kBase = split * 256;
    float* pout = pbuf + (long)split * PART_STRIDE;

    const int warp = tid >> 5, lane = tid & 31;
    const int wm = warp >> 1, wn = warp & 1;
    const int m0 = wm * 32, n0 = wn * 64;

    const uint32_t aoffs = (uint32_t)((m0 + (lane & 15)) * LDS_ROW + (lane >> 4) * 16);
    const uint32_t boffs = (uint32_t)((n0 + ((lane >> 4) & 1) * 8 + (lane & 7)) * LDS_ROW
                                      + ((lane >> 3) & 1) * 16);

    float acc[2][8][4];
    #pragma unroll
    for (int mi = 0; mi < 2; mi++)
        #pragma unroll
        for (int nj = 0; nj < 8; nj++)
            #pragma unroll
            for (int t = 0; t < 4; t++) acc[mi][nj][t] = 0.f;

    kv_load_stage(smb, 0, tid, part, colBase, kBase, ehi, elo, Bhi, Blo);

    const int NS = 8;   // 256 K per split
    for (int s = 0; s < NS; ++s) {
        if (s + 1 < NS) {
            kv_load_stage(smb, s + 1, tid, part, colBase, kBase, ehi, elo, Bhi, Blo);
            CP_WAIT(1);
        } else {
            CP_WAIT(0);
        }
        __syncthreads();

        const int b = s & 1;
        const uint32_t aHi = smb + OFF_AHI + b * ABUF;
        const uint32_t aLo = smb + OFF_ALO + b * ABUF;
        const uint32_t bHi = smb + OFF_BHI + b * ABUF;
        const uint32_t bLo = smb + OFF_BLO + b * ABUF;

        #pragma unroll
        for (int ks = 0; ks < 2; ks++) {
            uint32_t Ah[2][4], Al[2][4];
            #pragma unroll
            for (int mi = 0; mi < 2; mi++) {
                ldsm_x4(Ah[mi], aHi + aoffs + mi * 16 * LDS_ROW + ks * 32);
                ldsm_x4(Al[mi], aLo + aoffs + mi * 16 * LDS_ROW + ks * 32);
            }
            #pragma unroll
            for (int half = 0; half < 2; half++) {
                uint32_t Bh[2][4], Bl[2][4];
                #pragma unroll
                for (int nn = 0; nn < 2; nn++) {
                    const uint32_t bo = boffs + (half * 2 + nn) * 16 * LDS_ROW + ks * 32;
                    ldsm_x4(Bh[nn], bHi + bo);
                    ldsm_x4(Bl[nn], bLo + bo);
                }
                #pragma unroll
                for (int mi = 0; mi < 2; mi++) {
                    #pragma unroll
                    for (int j4 = 0; j4 < 4; j4++) {
                        const int ni = j4 >> 1, h = (j4 & 1) * 2;
                        float* a = acc[mi][half * 4 + j4];
                        mma16816(a, Ah[mi], Bh[ni][h], Bh[ni][h + 1]);
                        mma16816(a, Ah[mi], Bl[ni][h], Bl[ni][h + 1]);
                        mma16816(a, Al[mi], Bh[ni][h], Bh[ni][h + 1]);
                    }
                }
            }
        }
        __syncthreads();
    }

    // Epilogue: scatter fp32 partials by packed-row map
    const int g = lane >> 2, tig = lane & 3;
    #pragma unroll
    for (int mi = 0; mi < 2; mi++) {
        #pragma unroll
        for (int nj = 0; nj < 8; nj++) {
            const int r0 = m0 + mi * 16 + g;
            const int col = colBase + n0 + nj * 8 + tig * 2;
            long aR, cR;
            if (kv_map(part, r0, aR, cR))
                *(float2*)(pout + cR * HIDDEN + col) =
                    make_float2(acc[mi][nj][0], acc[mi][nj][1]);
            if (kv_map(part, r0 + 8, aR, cR))
                *(float2*)(pout + cR * HIDDEN + col) =
                    make_float2(acc[mi][nj][2], acc[mi][nj][3]);
        }
    }
}

// Sum 8 split-K partials + bf16 hi/lo split.
__global__ __launch_bounds__(256)
void reduce_split_kv(const float* __restrict__ part,
                     __nv_bfloat16* __restrict__ hi, __nv_bfloat16* __restrict__ lo)
{
    const long n4 = PART_STRIDE / 4;
    long i = (long)blockIdx.x * 256 + threadIdx.x;
    if (i >= n4) return;
    const float4* p4 = (const float4*)part;
    float4 s = p4[i];
    #pragma unroll
    for (int k = 1; k < 8; k++) {
        float4 t = p4[i + (long)k * n4];
        s.x += t.x; s.y += t.y; s.z += t.z; s.w += t.w;
    }
    __nv_bfloat16 h0 = __float2bfloat16(s.x);
    __nv_bfloat16 h1 = __float2bfloat16(s.y);
    __nv_bfloat16 h2 = __float2bfloat16(s.z);
    __nv_bfloat16 h3 = __float2bfloat16(s.w);
    __nv_bfloat162 hA; hA.x = h0; hA.y = h1;
    __nv_bfloat162 hB; hB.x = h2; hB.y = h3;
    ((uint2*)hi)[i] = make_uint2(*reinterpret_cast<uint32_t*>(&hA),
                                 *reinterpret_cast<uint32_t*>(&hB));
    uint32_t l01 = pack_bf16x2(s.x - __bfloat162float(h0), s.y - __bfloat162float(h1));
    uint32_t l23 = pack_bf16x2(s.z - __bfloat162float(h2), s.w - __bfloat162float(h3));
    ((uint2*)lo)[i] = make_uint2(l01, l23);
}

// ============================================================================
// HMMA flash attention: CTA = 128 q-rows x 96 keys (77 text + pad + 4 ip @80).
// 8 warps, warp = 16 rows. 3-term bf16 split. V [key][dim] + ldsm.trans.
// Writes hs as bf16 hi/lo split.
// ============================================================================
#define AROW 144
#define KROW 144
#define OFF_QHI 0
#define OFF_QLO (128 * AROW)                // 18432
#define OFF_KHI (2 * 128 * AROW)            // 36864
#define OFF_KLO (OFF_KHI + 96 * KROW)       // 50688
#define OFF_VHI (OFF_KLO + 96 * KROW)       // 64512
#define OFF_VLO (OFF_VHI + 96 * KROW)       // 78336
#define SMEM_ATTN (OFF_VLO + 96 * KROW)     // 92160

__global__ __launch_bounds__(256)
void attn_mma(const __nv_bfloat16* __restrict__ qhi,
              const __nv_bfloat16* __restrict__ qlo,
              const __nv_bfloat16* __restrict__ kvhi,
              const __nv_bfloat16* __restrict__ kvlo,
              __nv_bfloat16* __restrict__ ohi, __nv_bfloat16* __restrict__ olo)
{
    extern __shared__ __align__(16) char smx[];
    const uint32_t smb = smem_to_u32(smx);
    const int tid = threadIdx.x;
    const int b = blockIdx.z, h = blockIdx.y;
    const int rowBase = blockIdx.x * 128;
    const long SLAB = (long)NB * TXT * HIDDEN;   // per-gemm stride in kv

    // Q tile: 128 rows x 64 dims (hi+lo)
    #pragma unroll
    for (int i = 0; i < 4; i++) {
        int idx = tid + i * 256;
        int r = idx >> 3, c = idx & 7;
        long src = ((long)b * SQ + rowBase + r) * HIDDEN + h * 64 + c * 8;
        uint32_t d = smb + (uint32_t)(r * AROW + c * 16);
        cp_async16(d + OFF_QHI, qhi + src, 16);
        cp_async16(d + OFF_QLO, qlo + src, 16);
    }
    // K tile: 96 rows (0-76 text K, 80-83 ipK, rest zero)
    #pragma unroll
    for (int i = 0; i < 3; i++) {
        int idx = tid + i * 256;
        int r = idx >> 3, c = idx & 7;
        int bytes = 0;
        long src = 0;
        if (r < TXT) {
            bytes = 16;
            src = (long)b * TXT * HIDDEN + (long)r * HIDDEN + h * 64 + c * 8;
        } else if (r >= 80 && r < 80 + NTOK) {
            bytes = 16;
            src = 2 * SLAB + (long)b * TXT * HIDDEN + (long)(r - 80) * HIDDEN + h * 64 + c * 8;
        }
        uint32_t d = smb + OFF_KHI + (uint32_t)(r * KROW + c * 16);
        cp_async16(d, kvhi + src, bytes);
        cp_async16(d + (OFF_KLO - OFF_KHI), kvlo + src, bytes);
    }
    // V tile: 96 rows (0-76 text V, 80-83 ipV, rest zero), [key][dim]
    #pragma unroll
    for (int i = 0; i < 3; i++) {
        int idx = tid + i * 256;
        int r = idx >> 3, c = idx & 7;
        int bytes = 0;
        long src = 0;
        if (r < TXT) {
            bytes = 16;
            src = SLAB + (long)b * TXT * HIDDEN + (long)r * HIDDEN + h * 64 + c * 8;
        } else if (r >= 80 && r < 80 + NTOK) {
            bytes = 16;
            src = 3 * SLAB + (long)b * TXT * HIDDEN + (long)(r - 80) * HIDDEN + h * 64 + c * 8;
        }
        uint32_t d = smb + OFF_VHI + (uint32_t)(r * KROW + c * 16);
        cp_async16(d, kvhi + src, bytes);
        cp_async16(d + (OFF_VLO - OFF_VHI), kvlo + src, bytes);
    }
    CP_COMMIT();
    CP_WAIT(0);
    __syncthreads();

    const int warp = tid >> 5, lane = tid & 31;
    const int m0 = warp * 16;
    const int tig = lane & 3;
    const uint32_t aoffs = smb + (uint32_t)((m0 + (lane & 15)) * AROW + (lane >> 4) * 16);
    const uint32_t kbase = smb + OFF_KHI
        + (uint32_t)((((lane >> 4) & 1) * 8 + (lane & 7)) * KROW + ((lane >> 3) & 1) * 16);

    // S = Q K^T (12 n-tiles of 8 keys = 96)
    float s[12][4];
    #pragma unroll
    for (int j = 0; j < 12; j++)
        #pragma unroll
        for (int e = 0; e < 4; e++) s[j][e] = 0.f;

    #pragma unroll
    for (int ks = 0; ks < 4; ks++) {
        uint32_t Qh[4], Ql[4];
        ldsm_x4(Qh, aoffs + ks * 32);
        ldsm_x4(Ql, aoffs + OFF_QLO + ks * 32);
        #pragma unroll
        for (int t = 0; t < 6; t++) {
            uint32_t Bh[4], Bl[4];
            ldsm_x4(Bh, kbase + t * 16 * KROW + ks * 32);
            ldsm_x4(Bl, kbase + (OFF_KLO - OFF_KHI) + t * 16 * KROW + ks * 32);
            #pragma unroll
            for (int half = 0; half < 2; half++) {
                const int j = 2 * t + half, hh = half * 2;
                mma16816(s[j], Qh, Bh[hh], Bh[hh + 1]);
                mma16816(s[j], Qh, Bl[hh], Bl[hh + 1]);
                mma16816(s[j], Ql, Bh[hh], Bh[hh + 1]);
            }
        }
    }

    // scale + mask
    const bool ipOn = (b & 1);
    float mx[2]  = {-1e30f, -1e30f};
    float mx2[2] = {-1e30f, -1e30f};
    #pragma unroll
    for (int j = 0; j < 10; j++)
        #pragma unroll
        for (int e = 0; e < 4; e++) {
            int col = j * 8 + tig * 2 + (e & 1);
            float v = s[j][e] * 0.125f;
            s[j][e] = (col < TXT) ? v : -1e30f;
            mx[e >> 1] = fmaxf(mx[e >> 1], s[j][e]);
        }
    #pragma unroll
    for (int j = 10; j < 12; j++)
        #pragma unroll
        for (int e = 0; e < 4; e++) {
            int col = j * 8 + tig * 2 + (e & 1);
            float v = s[j][e] * 0.125f;
            s[j][e] = (col >= 80 && col < 80 + NTOK) ? v : -1e30f;
            mx2[e >> 1] = fmaxf(mx2[e >> 1], s[j][e]);
        }
    #pragma unroll
    for (int off = 1; off <= 2; off <<= 1) {
        mx[0]  = fmaxf(mx[0],  __shfl_xor_sync(0xffffffffu, mx[0],  off));
        mx[1]  = fmaxf(mx[1],  __shfl_xor_sync(0xffffffffu, mx[1],  off));
        mx2[0] = fmaxf(mx2[0], __shfl_xor_sync(0xffffffffu, mx2[0], off));
        mx2[1] = fmaxf(mx2[1], __shfl_xor_sync(0xffffffffu, mx2[1], off));
    }
    float l[2] = {0.f, 0.f}, l2[2] = {0.f, 0.f};
    #pragma unroll
    for (int j = 0; j < 10; j++)
        #pragma unroll
        for (int e = 0; e < 4; e++) {
            float p = __expf(s[j][e] - mx[e >> 1]);
            s[j][e] = p;
            l[e >> 1] += p;
        }
    #pragma unroll
    for (int j = 10; j < 12; j++)
        #pragma unroll
        for (int e = 0; e < 4; e++) {
            float p = __expf(s[j][e] - mx2[e >> 1]);
            s[j][e] = p;
            l2[e >> 1] += p;
        }
    #pragma unroll
    for (int off = 1; off <= 2; off <<= 1) {
        l[0]  += __shfl_xor_sync(0xffffffffu, l[0],  off);
        l[1]  += __shfl_xor_sync(0xffffffffu, l[1],  off);
        l2[0] += __shfl_xor_sync(0xffffffffu, l2[0], off);
        l2[1] += __shfl_xor_sync(0xffffffffu, l2[1], off);
    }
    float inv[2], inv2[2];
    inv[0] = 1.f / l[0];
    inv[1] = 1.f / l[1];
    inv2[0] = ipOn ? 1.f / l2[0] : 0.f;
    inv2[1] = ipOn ? 1.f / l2[1] : 0.f;
    #pragma unroll
    for (int j = 0; j < 10; j++)
        #pragma unroll
        for (int e = 0; e < 4; e++) s[j][e] *= inv[e >> 1];
    #pragma unroll
    for (int j = 10; j < 12; j++)
        #pragma unroll
        for (int e = 0; e < 4; e++) s[j][e] *= inv2[e >> 1];

    // PV via ldsm.trans on V[key][dim]
    const uint32_t vtbase = smb + OFF_VHI
        + (uint32_t)((((lane >> 3) & 1) * 8 + (lane & 7)) * KROW + ((lane >> 4) & 1) * 16);
    float out[8][4];
    #pragma unroll
    for (int d = 0; d < 8; d++)
        #pragma unroll
        for (int e = 0; e < 4; e++) out[d][e] = 0.f;

    #pragma unroll
    for (int kk = 0; kk < 6; kk++) {
        uint32_t ah[4], al[4];
        #pragma unroll
        for (int r = 0; r < 4; r++) {
            const int t = 2 * kk + (r >> 1);
            const int pi = (r & 1) * 2;
            float v0 = s[t][pi], v1 = s[t][pi + 1];
            __nv_bfloat16 h0 = __float2bfloat16(v0);
            __nv_bfloat16 h1 = __float2bfloat16(v1);
            __nv_bfloat162 hh; hh.x = h0; hh.y = h1;
            ah[r] = *reinterpret_cast<uint32_t*>(&hh);
            al[r] = pack_bf16x2(v0 - __bfloat162float(h0), v1 - __bfloat162float(h1));
        }
        #pragma unroll
        for (int d = 0; d < 4; d++) {
            uint32_t Vh[4], Vl[4];
            ldsm_x4_t(Vh, vtbase + kk * 16 * KROW + d * 32);
            ldsm_x4_t(Vl, vtbase + (OFF_VLO - OFF_VHI) + kk * 16 * KROW + d * 32);
            #pragma unroll
            for (int half = 0; half < 2; half++) {
                const int j = 2 * d + half, hh = half * 2;
                mma16816(out[j], ah, Vh[hh], Vh[hh + 1]);
                mma16816(out[j], ah, Vl[hh], Vl[hh + 1]);
                mma16816(out[j], al, Vh[hh], Vh[hh + 1]);
            }
        }
    }

    // write hs bf16 hi/lo split
    const int g = lane >> 2;
    const long row0 = (long)b * SQ + rowBase + m0 + g;
    #pragma unroll
    for (int d = 0; d < 8; d++) {
        const int col = h * 64 + d * 8 + tig * 2;
        #pragma unroll
        for (int rr = 0; rr < 2; rr++) {
            float v0 = out[d][rr * 2 + 0], v1 = out[d][rr * 2 + 1];
            long o = (row0 + rr * 8) * HIDDEN + col;
            __nv_bfloat16 h0 = __float2bfloat16(v0);
            __nv_bfloat16 h1 = __float2bfloat16(v1);
            __nv_bfloat162 hh; hh.x = h0; hh.y = h1;
            *(uint32_t*)(ohi + o) = *reinterpret_cast<uint32_t*>(&hh);
            *(uint32_t*)(olo + o) = pack_bf16x2(
                v0 - __bfloat162float(h0), v1 - __bfloat162float(h1));
        }
    }
}

// ============================================================================
// Launcher
// ============================================================================
extern "C" void kernel_launch(void* const* d_in, const int* in_sizes, int n_in,
                              void* d_out, int out_size)
{
    const float* hidden = (const float*)d_in[0];
    const float* enc    = (const float*)d_in[1];
    const float* Wq     = (const float*)d_in[2];
    const float* Wk     = (const float*)d_in[3];
    const float* Wv     = (const float*)d_in[4];
    const float* Wk_ip  = (const float*)d_in[5];
    const float* Wv_ip  = (const float*)d_in[6];
    const float* Wout   = (const float*)d_in[7];
    const float* b_out  = (const float*)d_in[8];
    float* out = (float*)d_out;

    static bool attr_set = false;
    if (!attr_set) {
        cudaFuncSetAttribute(hmma_gemm, cudaFuncAttributeMaxDynamicSharedMemorySize, SMEM_TOT);
        cudaFuncSetAttribute(hmma_gemm_kv, cudaFuncAttributeMaxDynamicSharedMemorySize, SMEM_TOT);
        cudaFuncSetAttribute(attn_mma, cudaFuncAttributeMaxDynamicSharedMemorySize, SMEM_ATTN);
        attr_set = true;
    }

    __nv_bfloat16 *ahi, *alo, *qhi, *qlo, *ehi, *elo;
    __nv_bfloat16 *wqh, *wql, *wth, *wtl, *woh, *wol, *kvh, *kvl;
    float* pbuf;
    cudaGetSymbolAddress((void**)&ahi, g_ahi);
    cudaGetSymbolAddress((void**)&alo, g_alo);
    cudaGetSymbolAddress((void**)&qhi, g_qhi);
    cudaGetSymbolAddress((void**)&qlo, g_qlo);
    cudaGetSymbolAddress((void**)&ehi, g_ehi);
    cudaGetSymbolAddress((void**)&elo, g_elo);
    cudaGetSymbolAddress((void**)&wqh, g_wqT_hi);
    cudaGetSymbolAddress((void**)&wql, g_wqT_lo);
    cudaGetSymbolAddress((void**)&wth, g_wT_hi);
    cudaGetSymbolAddress((void**)&wtl, g_wT_lo);
    cudaGetSymbolAddress((void**)&woh, g_woutT_hi);
    cudaGetSymbolAddress((void**)&wol, g_woutT_lo);
    cudaGetSymbolAddress((void**)&kvh, g_kvhi);
    cudaGetSymbolAddress((void**)&kvl, g_kvlo);
    cudaGetSymbolAddress((void**)&pbuf, g_part);

    const int M_big = NB * SQ;  // 16384
    const long WSLAB = (long)HIDDEN * CROSS;

    // 1) activation splits
    {
        int n4 = M_big * HIDDEN / 4;
        split_kernel<<<(n4 + 255) / 256, 256>>>(hidden, ahi, alo, n4);
    }
    {
        int n4 = NB * ENC * CROSS / 4;
        split_kernel<<<(n4 + 255) / 256, 256>>>(enc, ehi, elo, n4);
    }

    // 2) all weight transposes+splits in one launch
    {
        TSArgs t;
        t.src[0] = Wq;    t.dhi[0] = wqh;             t.dlo[0] = wql;             t.K[0] = HIDDEN;
        t.src[1] = Wk;    t.dhi[1] = wth + 0 * WSLAB; t.dlo[1] = wtl + 0 * WSLAB; t.K[1] = CROSS;
        t.src[2] = Wv;    t.dhi[2] = wth + 1 * WSLAB; t.dlo[2] = wtl + 1 * WSLAB; t.K[2] = CROSS;
        t.src[3] = Wk_ip; t.dhi[3] = wth + 2 * WSLAB; t.dlo[3] = wtl + 2 * WSLAB; t.K[3] = CROSS;
        t.src[4] = Wv_ip; t.dhi[4] = wth + 3 * WSLAB; t.dlo[4] = wtl + 3 * WSLAB; t.K[4] = CROSS;
        t.src[5] = Wout;  t.dhi[5] = woh;             t.dlo[5] = wol;             t.K[5] = HIDDEN;
        transpose_split_all<<<dim3(HIDDEN / 32, CROSS / 32, 6), dim3(32, 8)>>>(t);
    }

    // 3) Q = hidden @ Wq  -> bf16 hi/lo split
    {
        GemmArgs a = {ahi, alo, wqh, wql, nullptr, qhi, qlo,
                      M_big, HIDDEN, HIDDEN, nullptr, nullptr};
        hmma_gemm<<<dim3(HIDDEN / 128, M_big / 128, 1), 256, SMEM_TOT>>>(a);
    }

    // 4) packed split-K K/V/ipK/ipV projections -> fp32 partials -> reduce+split
    hmma_gemm_kv<<<dim3(HIDDEN / 128, 8, 8), 256, SMEM_TOT>>>(ehi, elo, wth, wtl, pbuf);
    {
        long n4 = PART_STRIDE / 4;
        reduce_split_kv<<<(int)((n4 + 255) / 256), 256>>>(pbuf, kvh, kvl);
    }

    // 5) HMMA attention -> hs bf16 hi/lo (reuses ahi/alo)
    attn_mma<<<dim3(SQ / 128, NHEADS, NB), 256, SMEM_ATTN>>>(qhi, qlo, kvh, kvl, ahi, alo);

    // 6) out = hs @ Wout + b_out + residual (fp32)
    {
        GemmArgs a = {ahi, alo, woh, wol, out, nullptr, nullptr,
                      M_big, HIDDEN, HIDDEN, b_out, hidden};
        hmma_gemm<<<dim3(HIDDEN / 128, M_big / 128, 1), 256, SMEM_TOT>>>(a);
    }
}